// round 10
// baseline (speedup 1.0000x reference)
#include <cuda_runtime.h>
#include <cuda_fp16.h>
#include <stdint.h>

constexpr int Bc = 4, Hc = 16, Pp = 1024, Dd = 128;
constexpr int NELEM = Bc * Hc * Pp * Dd;   // 8388608
constexpr int BM = 32;       // query rows per CTA
constexpr int TN = 128;      // keys per tile
constexpr int NT = Pp / TN;  // 8 tiles

// ---- device scratch: silu'd k as fp16 (q is fused into pass 2) ----
__device__ __half g_kh[NELEM];

// ---- smem layout (bytes) ----
constexpr int OFF_Q   = 0;        // 32 rows x 256B (swizzled) = 8192
constexpr int OFF_K   = 8192;     // 16 warps x 4 slots x 2KB = 131072
constexpr int OFF_SC  = 139264;   // 32 rows x 2048B fp16 scores = 65536
constexpr int OFF_RS  = 204800;   // 16 warps x 32 rows x 4B = 2048
constexpr int OFF_INV = 206848;   // 32 x 4B
constexpr int SMEM2   = 206976;

// =================== helpers ===================
__device__ __forceinline__ uint32_t smem_u32(const void* p) {
    uint32_t a;
    asm("{ .reg .u64 t; cvta.to.shared.u64 t, %1; cvt.u32.u64 %0, t; }" : "=r"(a) : "l"(p));
    return a;
}
__device__ __forceinline__ void cpa16(uint32_t dst, const void* src) {
    asm volatile("cp.async.cg.shared.global [%0], [%1], 16;" :: "r"(dst), "l"(src));
}
__device__ __forceinline__ void cpa_commit() { asm volatile("cp.async.commit_group;" ::: "memory"); }
template<int N>
__device__ __forceinline__ void cpa_wait() { asm volatile("cp.async.wait_group %0;" :: "n"(N) : "memory"); }

__device__ __forceinline__ void ldsm4(uint32_t* r, uint32_t addr) {
    asm volatile("ldmatrix.sync.aligned.m8n8.x4.shared.b16 {%0,%1,%2,%3}, [%4];"
                 : "=r"(r[0]), "=r"(r[1]), "=r"(r[2]), "=r"(r[3]) : "r"(addr));
}
__device__ __forceinline__ void ldsm2(uint32_t* r, uint32_t addr) {
    asm volatile("ldmatrix.sync.aligned.m8n8.x2.shared.b16 {%0,%1}, [%2];"
                 : "=r"(r[0]), "=r"(r[1]) : "r"(addr));
}
__device__ __forceinline__ void mma16816(float* d, const uint32_t* a, uint32_t b0, uint32_t b1) {
    asm volatile(
        "mma.sync.aligned.m16n8k16.row.col.f32.f16.f16.f32 "
        "{%0,%1,%2,%3}, {%4,%5,%6,%7}, {%8,%9}, {%0,%1,%2,%3};"
        : "+f"(d[0]), "+f"(d[1]), "+f"(d[2]), "+f"(d[3])
        : "r"(a[0]), "r"(a[1]), "r"(a[2]), "r"(a[3]), "r"(b0), "r"(b1));
}
__device__ __forceinline__ void sts32(uint32_t addr, uint32_t v) {
    asm volatile("st.shared.u32 [%0], %1;" :: "r"(addr), "r"(v) : "memory");
}
__device__ __forceinline__ void sts128(uint32_t addr, uint4 v) {
    asm volatile("st.shared.v4.b32 [%0], {%1,%2,%3,%4};"
                 :: "r"(addr), "r"(v.x), "r"(v.y), "r"(v.z), "r"(v.w) : "memory");
}
__device__ __forceinline__ void lds64(uint32_t& a, uint32_t& b, uint32_t addr) {
    asm volatile("ld.shared.v2.u32 {%0,%1}, [%2];" : "=r"(a), "=r"(b) : "r"(addr));
}
__device__ __forceinline__ float silu_f(float x) {
    return x * (1.0f / (1.0f + __expf(-x)));
}
__device__ __forceinline__ uint32_t pack_h2(__half a, __half b) {
    __half2 t(a, b);
    return *reinterpret_cast<uint32_t*>(&t);
}
__device__ __forceinline__ uint32_t f2h2(float a, float b) {
    __half2 t = __floats2half2_rn(a, b);
    return *reinterpret_cast<uint32_t*>(&t);
}

// =================== Pass 1: silu -> fp16 (k only) ===================
__global__ void __launch_bounds__(256)
silu_k_kernel(const float* __restrict__ k)
{
    int j = blockIdx.x * 256 + threadIdx.x;
    float4 vk = ((const float4*)k)[j];
    ((uint2*)g_kh)[j] = make_uint2(
        pack_h2(__float2half(silu_f(vk.x)), __float2half(silu_f(vk.y))),
        pack_h2(__float2half(silu_f(vk.z)), __float2half(silu_f(vk.w))));
}

// =================== Pass 2: HMMA GEMM + fused softmax ===================
// 512 threads = 16 fully independent warps. Warp w owns ALL 32 rows x keys
// [t*128 + w*8, +8) of every tile t. Q loaded fp32 + silu'd in-kernel; K in a
// warp-private 4-slot cp.async ring (no mainloop barriers). exp'd scores
// staged fp16 in smem; final phase does coalesced normalize+store.
__global__ void __launch_bounds__(512, 1)
attn_mma_kernel(const float* __restrict__ q,
                const float* __restrict__ scale_p, float* __restrict__ out)
{
    extern __shared__ char smem[];
    const uint32_t sb = smem_u32(smem);
    const int tid = threadIdx.x, lane = tid & 31, w = tid >> 5;
    const int mtile = blockIdx.x, bh = blockIdx.y;
    const float sc = scale_p[0];

    const char* khB = (const char*)g_kh + (size_t)bh * Pp * 256;
    const uint32_t myring = sb + OFF_K + (uint32_t)w * 8192;

    // warp-private slab: 8 keys x 256B for tile t -> slot t&3
    auto pfK = [&](int t) {
        uint32_t dst = myring + (uint32_t)(t & 3) * 2048;
        const char* src = khB + (size_t)(t * TN + w * 8) * 256;
        #pragma unroll
        for (int i = 0; i < 4; ++i) {
            int idx = lane + (i << 5);           // 0..127
            int key = idx >> 4, c = idx & 15;
            uint32_t off = (uint32_t)(key * 256) + (((c ^ (key & 7)) & 15) << 4);
            cpa16(dst + off, src + key * 256 + c * 16);
        }
        cpa_commit();
    };
    pfK(0); pfK(1); pfK(2); pfK(3);   // groups 0..3 (K stream starts first)

    // ---- Q tile: LDG fp32 -> silu -> fp16 -> swizzled STS.128 ----
    // thread tid handles chunk (row = tid>>4, c = tid&15) = dims [8c, 8c+8)
    {
        int row = tid >> 4, c = tid & 15;
        const float* qsrc = q + ((size_t)(bh * Pp + mtile * BM) + row) * Dd + c * 8;
        float4 v0 = *(const float4*)(qsrc);
        float4 v1 = *(const float4*)(qsrc + 4);
        uint4 hv;
        hv.x = pack_h2(__float2half(silu_f(v0.x)), __float2half(silu_f(v0.y)));
        hv.y = pack_h2(__float2half(silu_f(v0.z)), __float2half(silu_f(v0.w)));
        hv.z = pack_h2(__float2half(silu_f(v1.x)), __float2half(silu_f(v1.y)));
        hv.w = pack_h2(__float2half(silu_f(v1.z)), __float2half(silu_f(v1.w)));
        uint32_t off = row * 256 + (((c ^ (row & 7)) & 15) << 4);
        sts128(sb + OFF_Q + off, hv);
    }
    __syncthreads();    // Q visible to all warps

    // ---- hoist Q fragments (2 row-groups x 8 ks) ----
    const int lm = lane >> 3, lr = lane & 7;
    uint32_t aq[2][8][4];
    #pragma unroll
    for (int rg = 0; rg < 2; ++rg) {
        int arow = rg * 16 + ((lm & 1) << 3) + lr;
        uint32_t arow256 = (uint32_t)arow * 256;
        int ax7 = arow & 7, amc = lm >> 1;
        #pragma unroll
        for (int ks = 0; ks < 8; ++ks) {
            uint32_t ac = (uint32_t)((((2 * ks + amc) ^ ax7) & 15) << 4);
            ldsm4(aq[rg][ks], sb + OFF_Q + arow256 + ac);
        }
    }

    // B addressing (lanes 0-15 meaningful for ldsm.x2)
    const int brow = lane & 7;
    const int bsel = (lane >> 3) & 1;
    const uint32_t browoff = (uint32_t)brow * 256;
    const int r0 = lane >> 2;                       // 0..7
    const uint32_t rx = (uint32_t)((r0 & 7) << 4);  // score swizzle for this thread's rows
    const uint32_t kcolbyte = (uint32_t)(w * 16 + 4 * (lane & 3));
    const uint32_t scb = sb + OFF_SC;

    float s[4] = {0.f, 0.f, 0.f, 0.f};

    #pragma unroll
    for (int t = 0; t < NT; ++t) {
        // per-warp wait for slab t (no CTA barrier)
        if (t <= 4) cpa_wait<3>();
        else if (t == 5) cpa_wait<2>();
        else if (t == 6) cpa_wait<1>();
        else cpa_wait<0>();

        const uint32_t Kb = myring + (uint32_t)(t & 3) * 2048;
        float acc0[4] = {0.f, 0.f, 0.f, 0.f};
        float acc1[4] = {0.f, 0.f, 0.f, 0.f};

        #pragma unroll
        for (int ks = 0; ks < 8; ++ks) {
            uint32_t b2[2];
            uint32_t bc = (uint32_t)((((2 * ks + bsel) ^ brow) & 15) << 4);
            ldsm2(b2, Kb + browoff + bc);
            mma16816(acc0, aq[0][ks], b2[0], b2[1]);
            mma16816(acc1, aq[1][ks], b2[0], b2[1]);
        }

        if (t + 4 < NT) pfK(t + 4);   // refill slot t&3 (warp-private, reads done)

        // exp + fp32 sums + fp16 pack + swizzled STS
        uint32_t kb = (uint32_t)t * 256 + kcolbyte;
        float e0, e1;
        e0 = __expf(sc * acc0[0]); e1 = __expf(sc * acc0[1]); s[0] += e0 + e1;
        sts32(scb + (uint32_t)r0 * 2048        + (kb ^ rx), f2h2(e0, e1));
        e0 = __expf(sc * acc0[2]); e1 = __expf(sc * acc0[3]); s[1] += e0 + e1;
        sts32(scb + (uint32_t)(r0 + 8) * 2048  + (kb ^ rx), f2h2(e0, e1));
        e0 = __expf(sc * acc1[0]); e1 = __expf(sc * acc1[1]); s[2] += e0 + e1;
        sts32(scb + (uint32_t)(r0 + 16) * 2048 + (kb ^ rx), f2h2(e0, e1));
        e0 = __expf(sc * acc1[2]); e1 = __expf(sc * acc1[3]); s[3] += e0 + e1;
        sts32(scb + (uint32_t)(r0 + 24) * 2048 + (kb ^ rx), f2h2(e0, e1));
    }

    // ---- row sums: reduce over key-lanes (lane&3), then over warps ----
    #pragma unroll
    for (int o = 1; o < 4; o <<= 1) {
        s[0] += __shfl_xor_sync(0xFFFFFFFFu, s[0], o);
        s[1] += __shfl_xor_sync(0xFFFFFFFFu, s[1], o);
        s[2] += __shfl_xor_sync(0xFFFFFFFFu, s[2], o);
        s[3] += __shfl_xor_sync(0xFFFFFFFFu, s[3], o);
    }
    float* rs  = (float*)(smem + OFF_RS);
    float* inv = (float*)(smem + OFF_INV);
    if ((lane & 3) == 0) {
        rs[w * 32 + r0]      = s[0];
        rs[w * 32 + r0 + 8]  = s[1];
        rs[w * 32 + r0 + 16] = s[2];
        rs[w * 32 + r0 + 24] = s[3];
    }
    __syncthreads();   // also publishes all score STS
    if (tid < 32) {
        float tot = 0.0f;
        #pragma unroll
        for (int ww = 0; ww < 16; ++ww) tot += rs[ww * 32 + tid];
        inv[tid] = 1.0f / tot;
    }
    __syncthreads();

    // ---- coalesced normalize + store ----
    const int row = tid >> 4, cc = tid & 15;
    const float iv = inv[row];
    float* orow = out + ((size_t)bh * Pp + mtile * BM + row) * Pp;
    const uint32_t rbase = scb + (uint32_t)row * 2048;
    const uint32_t rxr = (uint32_t)((row & 7) << 4);
    #pragma unroll
    for (int p = 0; p < 16; ++p) {
        int key = cc * 4 + p * 64;
        uint32_t a, b;
        lds64(a, b, rbase + (((uint32_t)(key * 2)) ^ rxr));
        __half2 ha = *reinterpret_cast<__half2*>(&a);
        __half2 hb = *reinterpret_cast<__half2*>(&b);
        float2 fa = __half22float2(ha);
        float2 fb = __half22float2(hb);
        float4 v = make_float4(fa.x * iv, fa.y * iv, fb.x * iv, fb.y * iv);
        *(float4*)(orow + key) = v;
    }
}

// =================== launch ===================
extern "C" void kernel_launch(void* const* d_in, const int* in_sizes, int n_in,
                              void* d_out, int out_size)
{
    const float* q     = (const float*)d_in[0];
    const float* k     = (const float*)d_in[1];
    const float* scale = (const float*)d_in[2];
    float* out = (float*)d_out;

    silu_k_kernel<<<NELEM / 4 / 256, 256>>>(k);

    cudaFuncSetAttribute(attn_mma_kernel,
                         cudaFuncAttributeMaxDynamicSharedMemorySize, SMEM2);
    dim3 grid(Pp / BM, Bc * Hc);  // (32, 64)
    attn_mma_kernel<<<grid, 512, SMEM2>>>(q, scale, out);
}

// round 11
// speedup vs baseline: 1.1523x; 1.1523x over previous
#include <cuda_runtime.h>
#include <cuda_fp16.h>
#include <stdint.h>

constexpr int Bc = 4, Hc = 16, Pp = 1024, Dd = 128;
constexpr int NELEM = Bc * Hc * Pp * Dd;   // 8388608
constexpr int BM = 32;       // query rows per item
constexpr int TN = 128;      // keys per tile
constexpr int NT = Pp / TN;  // 8 tiles
constexpr int NITEMS = 2048; // 32 mtiles x 64 bh
constexpr int NCTAS = 152;   // GB300 SM count (1 CTA/SM, persistent)

// ---- device scratch: silu'd q, k as fp16 ----
__device__ __half g_qh[NELEM], g_kh[NELEM];

// ---- smem layout (bytes) ----
constexpr int OFF_Q   = 0;        // 32 rows x 256B (swizzled) = 8192
constexpr int OFF_K   = 8192;     // 16 warps x 4 slots x 2KB = 131072
constexpr int OFF_SC  = 139264;   // 32 rows x 2048B fp16 scores = 65536
constexpr int OFF_RS  = 204800;   // 16 warps x 32 rows x 4B = 2048
constexpr int OFF_INV = 206848;   // 32 x 4B
constexpr int SMEM2   = 206976;

// =================== helpers ===================
__device__ __forceinline__ uint32_t smem_u32(const void* p) {
    uint32_t a;
    asm("{ .reg .u64 t; cvta.to.shared.u64 t, %1; cvt.u32.u64 %0, t; }" : "=r"(a) : "l"(p));
    return a;
}
__device__ __forceinline__ void cpa16(uint32_t dst, const void* src) {
    asm volatile("cp.async.cg.shared.global [%0], [%1], 16;" :: "r"(dst), "l"(src));
}
__device__ __forceinline__ void cpa_commit() { asm volatile("cp.async.commit_group;" ::: "memory"); }
template<int N>
__device__ __forceinline__ void cpa_wait() { asm volatile("cp.async.wait_group %0;" :: "n"(N) : "memory"); }

__device__ __forceinline__ void ldsm4(uint32_t* r, uint32_t addr) {
    asm volatile("ldmatrix.sync.aligned.m8n8.x4.shared.b16 {%0,%1,%2,%3}, [%4];"
                 : "=r"(r[0]), "=r"(r[1]), "=r"(r[2]), "=r"(r[3]) : "r"(addr));
}
__device__ __forceinline__ void ldsm2(uint32_t* r, uint32_t addr) {
    asm volatile("ldmatrix.sync.aligned.m8n8.x2.shared.b16 {%0,%1}, [%2];"
                 : "=r"(r[0]), "=r"(r[1]) : "r"(addr));
}
__device__ __forceinline__ void mma16816(float* d, const uint32_t* a, uint32_t b0, uint32_t b1) {
    asm volatile(
        "mma.sync.aligned.m16n8k16.row.col.f32.f16.f16.f32 "
        "{%0,%1,%2,%3}, {%4,%5,%6,%7}, {%8,%9}, {%0,%1,%2,%3};"
        : "+f"(d[0]), "+f"(d[1]), "+f"(d[2]), "+f"(d[3])
        : "r"(a[0]), "r"(a[1]), "r"(a[2]), "r"(a[3]), "r"(b0), "r"(b1));
}
__device__ __forceinline__ void sts32(uint32_t addr, uint32_t v) {
    asm volatile("st.shared.u32 [%0], %1;" :: "r"(addr), "r"(v) : "memory");
}
__device__ __forceinline__ void lds64(uint32_t& a, uint32_t& b, uint32_t addr) {
    asm volatile("ld.shared.v2.u32 {%0,%1}, [%2];" : "=r"(a), "=r"(b) : "r"(addr));
}
__device__ __forceinline__ float silu_f(float x) {
    return x * (1.0f / (1.0f + __expf(-x)));
}
__device__ __forceinline__ uint32_t pack_h2(__half a, __half b) {
    __half2 t(a, b);
    return *reinterpret_cast<uint32_t*>(&t);
}
__device__ __forceinline__ uint32_t f2h2(float a, float b) {
    __half2 t = __floats2half2_rn(a, b);
    return *reinterpret_cast<uint32_t*>(&t);
}

// =================== Pass 1: silu -> fp16 ===================
__global__ void __launch_bounds__(256)
silu_split_kernel(const float* __restrict__ q, const float* __restrict__ k)
{
    int j = blockIdx.x * 256 + threadIdx.x;
    float4 vq = ((const float4*)q)[j];
    float4 vk = ((const float4*)k)[j];

    ((uint2*)g_qh)[j] = make_uint2(
        pack_h2(__float2half(silu_f(vq.x)), __float2half(silu_f(vq.y))),
        pack_h2(__float2half(silu_f(vq.z)), __float2half(silu_f(vq.w))));
    ((uint2*)g_kh)[j] = make_uint2(
        pack_h2(__float2half(silu_f(vk.x)), __float2half(silu_f(vk.y))),
        pack_h2(__float2half(silu_f(vk.z)), __float2half(silu_f(vk.w))));
}

// =================== Pass 2: persistent HMMA GEMM + fused softmax ===================
// 152 persistent CTAs x 512 threads (16 warp-private pipelines). Item = 32 query
// rows x one (b,h). Next item's Q + K-ring prologue is prefetched during the
// current item's epilogue, so only the very first item pays cold-start latency.
__global__ void __launch_bounds__(512, 1)
attn_mma_kernel(const float* __restrict__ scale_p, float* __restrict__ out)
{
    extern __shared__ char smem[];
    const uint32_t sb = smem_u32(smem);
    const int tid = threadIdx.x, lane = tid & 31, w = tid >> 5;
    const float sc = scale_p[0];

    const uint32_t myring = sb + OFF_K + (uint32_t)w * 8192;
    const uint32_t scb = sb + OFF_SC;
    float* rs  = (float*)(smem + OFF_RS);
    float* inv = (float*)(smem + OFF_INV);

    // Q chunk owned by this thread (row = tid>>4, c = tid&15)
    const int qrow = tid >> 4, qc = tid & 15;
    const uint32_t qoff = sb + OFF_Q + qrow * 256 + (((qc ^ (qrow & 7)) & 15) << 4);

    // issue Q group for item (1 chunk per thread)
    auto pfQ = [&](int item) {
        int bh = item >> 5, mtile = item & 31;
        const char* src = (const char*)g_qh +
            (((size_t)(bh * Pp + mtile * BM) + qrow) * 256 + qc * 16);
        cpa16(qoff, src);
        cpa_commit();
    };
    // warp-private K slab: 8 keys x 256B, tile t of item -> slot t&3
    auto pfK = [&](int item, int t) {
        int bh = item >> 5, mtile = item & 31;
        (void)mtile;
        uint32_t dst = myring + (uint32_t)(t & 3) * 2048;
        const char* src = (const char*)g_kh +
            ((size_t)(bh * Pp + t * TN + w * 8)) * 256;
        #pragma unroll
        for (int i = 0; i < 4; ++i) {
            int idx = lane + (i << 5);           // 0..127
            int key = idx >> 4, c = idx & 15;
            uint32_t off = (uint32_t)(key * 256) + (((c ^ (key & 7)) & 15) << 4);
            cpa16(dst + off, src + key * 256 + c * 16);
        }
        cpa_commit();
    };

    // fragment addressing constants
    const int lm = lane >> 3, lr = lane & 7;
    const int brow = lane & 7;
    const int bsel = (lane >> 3) & 1;
    const uint32_t browoff = (uint32_t)brow * 256;
    const int r0 = lane >> 2;                       // 0..7
    const uint32_t rx = (uint32_t)((r0 & 7) << 4);
    const uint32_t kcolbyte = (uint32_t)(w * 16 + 4 * (lane & 3));

    int item = blockIdx.x;
    if (item < NITEMS) {
        pfQ(item);                                   // group: Q
        #pragma unroll
        for (int t = 0; t < 4; ++t) pfK(item, t);    // groups: K0..K3
    }

    while (item < NITEMS) {
        const int next = item + NCTAS;
        const int bh = item >> 5, mtile = item & 31;

        cpa_wait<4>();      // Q arrived (K0..K3 may be pending)
        __syncthreads();    // Q visible CTA-wide; score buffer free for reuse

        // ---- hoist Q fragments (2 row-groups x 8 ks) ----
        uint32_t aq[2][8][4];
        #pragma unroll
        for (int rg = 0; rg < 2; ++rg) {
            int arow = rg * 16 + ((lm & 1) << 3) + lr;
            uint32_t arow256 = (uint32_t)arow * 256;
            int ax7 = arow & 7, amc = lm >> 1;
            #pragma unroll
            for (int ks = 0; ks < 8; ++ks) {
                uint32_t ac = (uint32_t)((((2 * ks + amc) ^ ax7) & 15) << 4);
                ldsm4(aq[rg][ks], sb + OFF_Q + arow256 + ac);
            }
        }

        float s[4] = {0.f, 0.f, 0.f, 0.f};

        #pragma unroll
        for (int t = 0; t < NT; ++t) {
            // per-warp wait for slab t (same ladder as non-persistent version)
            if (t <= 4) cpa_wait<3>();
            else if (t == 5) cpa_wait<2>();
            else if (t == 6) cpa_wait<1>();
            else cpa_wait<0>();

            const uint32_t Kb = myring + (uint32_t)(t & 3) * 2048;
            float acc0[4] = {0.f, 0.f, 0.f, 0.f};
            float acc1[4] = {0.f, 0.f, 0.f, 0.f};

            #pragma unroll
            for (int ks = 0; ks < 8; ++ks) {
                uint32_t b2[2];
                uint32_t bc = (uint32_t)((((2 * ks + bsel) ^ brow) & 15) << 4);
                ldsm2(b2, Kb + browoff + bc);
                mma16816(acc0, aq[0][ks], b2[0], b2[1]);
                mma16816(acc1, aq[1][ks], b2[0], b2[1]);
            }

            if (t + 4 < NT) pfK(item, t + 4);   // refill slot t&3

            // exp + fp32 sums + fp16 pack + swizzled STS
            uint32_t kb = (uint32_t)t * 256 + kcolbyte;
            float e0, e1;
            e0 = __expf(sc * acc0[0]); e1 = __expf(sc * acc0[1]); s[0] += e0 + e1;
            sts32(scb + (uint32_t)r0 * 2048        + (kb ^ rx), f2h2(e0, e1));
            e0 = __expf(sc * acc0[2]); e1 = __expf(sc * acc0[3]); s[1] += e0 + e1;
            sts32(scb + (uint32_t)(r0 + 8) * 2048  + (kb ^ rx), f2h2(e0, e1));
            e0 = __expf(sc * acc1[0]); e1 = __expf(sc * acc1[1]); s[2] += e0 + e1;
            sts32(scb + (uint32_t)(r0 + 16) * 2048 + (kb ^ rx), f2h2(e0, e1));
            e0 = __expf(sc * acc1[2]); e1 = __expf(sc * acc1[3]); s[3] += e0 + e1;
            sts32(scb + (uint32_t)(r0 + 24) * 2048 + (kb ^ rx), f2h2(e0, e1));
        }

        // ---- prefetch next item's Q + K prologue (overlaps epilogue) ----
        if (next < NITEMS) {
            pfQ(next);
            #pragma unroll
            for (int t = 0; t < 4; ++t) pfK(next, t);
        }

        // ---- row sums: reduce over key-lanes, then over warps ----
        #pragma unroll
        for (int o = 1; o < 4; o <<= 1) {
            s[0] += __shfl_xor_sync(0xFFFFFFFFu, s[0], o);
            s[1] += __shfl_xor_sync(0xFFFFFFFFu, s[1], o);
            s[2] += __shfl_xor_sync(0xFFFFFFFFu, s[2], o);
            s[3] += __shfl_xor_sync(0xFFFFFFFFu, s[3], o);
        }
        if ((lane & 3) == 0) {
            rs[w * 32 + r0]      = s[0];
            rs[w * 32 + r0 + 8]  = s[1];
            rs[w * 32 + r0 + 16] = s[2];
            rs[w * 32 + r0 + 24] = s[3];
        }
        __syncthreads();   // publishes all score STS + rs
        if (tid < 32) {
            float tot = 0.0f;
            #pragma unroll
            for (int ww = 0; ww < 16; ++ww) tot += rs[ww * 32 + tid];
            inv[tid] = 1.0f / tot;
        }
        __syncthreads();

        // ---- coalesced normalize + store ----
        const int row = tid >> 4, cc = tid & 15;
        const float iv = inv[row];
        float* orow = out + ((size_t)bh * Pp + mtile * BM + row) * Pp;
        const uint32_t rbase = scb + (uint32_t)row * 2048;
        const uint32_t rxr = (uint32_t)((row & 7) << 4);
        #pragma unroll
        for (int p = 0; p < 16; ++p) {
            int key = cc * 4 + p * 64;
            uint32_t a, b;
            lds64(a, b, rbase + (((uint32_t)(key * 2)) ^ rxr));
            __half2 ha = *reinterpret_cast<__half2*>(&a);
            __half2 hb = *reinterpret_cast<__half2*>(&b);
            float2 fa = __half22float2(ha);
            float2 fb = __half22float2(hb);
            float4 v = make_float4(fa.x * iv, fa.y * iv, fb.x * iv, fb.y * iv);
            *(float4*)(orow + key) = v;
        }

        item = next;
    }
}

// =================== launch ===================
extern "C" void kernel_launch(void* const* d_in, const int* in_sizes, int n_in,
                              void* d_out, int out_size)
{
    const float* q     = (const float*)d_in[0];
    const float* k     = (const float*)d_in[1];
    const float* scale = (const float*)d_in[2];
    float* out = (float*)d_out;

    silu_split_kernel<<<NELEM / 4 / 256, 256>>>(q, k);

    cudaFuncSetAttribute(attn_mma_kernel,
                         cudaFuncAttributeMaxDynamicSharedMemorySize, SMEM2);
    attn_mma_kernel<<<NCTAS, 512, SMEM2>>>(scale, out);
}

// round 12
// speedup vs baseline: 1.1740x; 1.0189x over previous
#include <cuda_runtime.h>
#include <cuda_fp16.h>
#include <stdint.h>

constexpr int Bc = 4, Hc = 16, Pp = 1024, Dd = 128;
constexpr int NELEM = Bc * Hc * Pp * Dd;   // 8388608
constexpr int BM = 32;       // query rows per item
constexpr int TN = 128;      // keys per tile
constexpr int NT = Pp / TN;  // 8 tiles
constexpr int NITEMS = 2048; // 32 mtiles x 64 bh
constexpr int NCTAS = 152;   // GB300 SM count (1 CTA/SM, persistent)

// ---- device scratch: silu'd q, k as fp16 ----
__device__ __half g_qh[NELEM], g_kh[NELEM];

// ---- smem layout (bytes) ----
constexpr int OFF_Q   = 0;        // 32 rows x 256B (swizzled) = 8192
constexpr int OFF_K   = 8192;     // 16 warps x 4 slots x 2KB = 131072
constexpr int OFF_SC  = 139264;   // 32 rows x 2048B fp16 scores = 65536
constexpr int OFF_RS  = 204800;   // 32 rows x 16 warps x 4B = 2048 (row-major)
constexpr int OFF_INV = 206848;   // 32 x 4B
constexpr int SMEM2   = 206976;

// =================== helpers ===================
__device__ __forceinline__ uint32_t smem_u32(const void* p) {
    uint32_t a;
    asm("{ .reg .u64 t; cvta.to.shared.u64 t, %1; cvt.u32.u64 %0, t; }" : "=r"(a) : "l"(p));
    return a;
}
__device__ __forceinline__ void cpa16(uint32_t dst, const void* src) {
    asm volatile("cp.async.cg.shared.global [%0], [%1], 16;" :: "r"(dst), "l"(src));
}
__device__ __forceinline__ void cpa_commit() { asm volatile("cp.async.commit_group;" ::: "memory"); }
template<int N>
__device__ __forceinline__ void cpa_wait() { asm volatile("cp.async.wait_group %0;" :: "n"(N) : "memory"); }

__device__ __forceinline__ void ldsm4(uint32_t* r, uint32_t addr) {
    asm volatile("ldmatrix.sync.aligned.m8n8.x4.shared.b16 {%0,%1,%2,%3}, [%4];"
                 : "=r"(r[0]), "=r"(r[1]), "=r"(r[2]), "=r"(r[3]) : "r"(addr));
}
__device__ __forceinline__ void mma16816(float* d, const uint32_t* a, uint32_t b0, uint32_t b1) {
    asm volatile(
        "mma.sync.aligned.m16n8k16.row.col.f32.f16.f16.f32 "
        "{%0,%1,%2,%3}, {%4,%5,%6,%7}, {%8,%9}, {%0,%1,%2,%3};"
        : "+f"(d[0]), "+f"(d[1]), "+f"(d[2]), "+f"(d[3])
        : "r"(a[0]), "r"(a[1]), "r"(a[2]), "r"(a[3]), "r"(b0), "r"(b1));
}
__device__ __forceinline__ void sts32(uint32_t addr, uint32_t v) {
    asm volatile("st.shared.u32 [%0], %1;" :: "r"(addr), "r"(v) : "memory");
}
__device__ __forceinline__ void lds64(uint32_t& a, uint32_t& b, uint32_t addr) {
    asm volatile("ld.shared.v2.u32 {%0,%1}, [%2];" : "=r"(a), "=r"(b) : "r"(addr));
}
__device__ __forceinline__ float silu_f(float x) {
    return x * (1.0f / (1.0f + __expf(-x)));
}
__device__ __forceinline__ uint32_t pack_h2(__half a, __half b) {
    __half2 t(a, b);
    return *reinterpret_cast<uint32_t*>(&t);
}
__device__ __forceinline__ uint32_t f2h2(float a, float b) {
    __half2 t = __floats2half2_rn(a, b);
    return *reinterpret_cast<uint32_t*>(&t);
}

// =================== Pass 1: silu -> fp16 (8 elems/thread) ===================
__global__ void __launch_bounds__(256)
silu_split_kernel(const float* __restrict__ q, const float* __restrict__ k)
{
    int j = blockIdx.x * 256 + threadIdx.x;   // 8-elem group index
    const float4* q4 = (const float4*)q + (size_t)j * 2;
    const float4* k4 = (const float4*)k + (size_t)j * 2;
    float4 a = q4[0], b = q4[1];
    uint4 o;
    o.x = pack_h2(__float2half(silu_f(a.x)), __float2half(silu_f(a.y)));
    o.y = pack_h2(__float2half(silu_f(a.z)), __float2half(silu_f(a.w)));
    o.z = pack_h2(__float2half(silu_f(b.x)), __float2half(silu_f(b.y)));
    o.w = pack_h2(__float2half(silu_f(b.z)), __float2half(silu_f(b.w)));
    ((uint4*)g_qh)[j] = o;
    a = k4[0]; b = k4[1];
    o.x = pack_h2(__float2half(silu_f(a.x)), __float2half(silu_f(a.y)));
    o.y = pack_h2(__float2half(silu_f(a.z)), __float2half(silu_f(a.w)));
    o.z = pack_h2(__float2half(silu_f(b.x)), __float2half(silu_f(b.y)));
    o.w = pack_h2(__float2half(silu_f(b.z)), __float2half(silu_f(b.w)));
    ((uint4*)g_kh)[j] = o;
}

// =================== Pass 2: persistent HMMA GEMM + fused softmax ===================
// 152 persistent CTAs x 512 threads (16 warp-private pipelines). Item = 32 query
// rows x one (b,h). B fragments for two ks-steps fetched in ONE ldsm.x4 via
// bsel = (lane>>3)&3. Next item's Q + K prologue prefetched during epilogue.
__global__ void __launch_bounds__(512, 1)
attn_mma_kernel(const float* __restrict__ scale_p, float* __restrict__ out)
{
    extern __shared__ char smem[];
    const uint32_t sb = smem_u32(smem);
    const int tid = threadIdx.x, lane = tid & 31, w = tid >> 5;
    const float sc = scale_p[0];

    const uint32_t myring = sb + OFF_K + (uint32_t)w * 8192;
    const uint32_t scb = sb + OFF_SC;
    float* rs  = (float*)(smem + OFF_RS);    // [32 rows][16 warps]
    float* inv = (float*)(smem + OFF_INV);

    // Q chunk owned by this thread (row = tid>>4, c = tid&15)
    const int qrow = tid >> 4, qc = tid & 15;
    const uint32_t qoff = sb + OFF_Q + qrow * 256 + (((qc ^ (qrow & 7)) & 15) << 4);

    auto pfQ = [&](int item) {
        int bh = item >> 5, mtile = item & 31;
        const char* src = (const char*)g_qh +
            (((size_t)(bh * Pp + mtile * BM) + qrow) * 256 + qc * 16);
        cpa16(qoff, src);
        cpa_commit();
    };
    auto pfK = [&](int item, int t) {
        int bh = item >> 5;
        uint32_t dst = myring + (uint32_t)(t & 3) * 2048;
        const char* src = (const char*)g_kh +
            ((size_t)(bh * Pp + t * TN + w * 8)) * 256;
        #pragma unroll
        for (int i = 0; i < 4; ++i) {
            int idx = lane + (i << 5);           // 0..127
            int key = idx >> 4, c = idx & 15;
            uint32_t off = (uint32_t)(key * 256) + (((c ^ (key & 7)) & 15) << 4);
            cpa16(dst + off, src + key * 256 + c * 16);
        }
        cpa_commit();
    };

    // fragment addressing constants
    const int lm = lane >> 3, lr = lane & 7;
    const int brow = lane & 7;
    const int bsel = (lane >> 3) & 3;     // 2-bit: selects chunk among {ks lo/hi, ks+1 lo/hi}
    const uint32_t browoff = (uint32_t)brow * 256;
    const int r0 = lane >> 2;                       // 0..7
    const uint32_t rx = (uint32_t)((r0 & 7) << 4);
    const uint32_t kcolbyte = (uint32_t)(w * 16 + 4 * (lane & 3));

    int item = blockIdx.x;
    if (item < NITEMS) {
        pfQ(item);
        #pragma unroll
        for (int t = 0; t < 4; ++t) pfK(item, t);
    }

    while (item < NITEMS) {
        const int next = item + NCTAS;
        const int bh = item >> 5, mtile = item & 31;

        cpa_wait<4>();      // Q arrived (K0..K3 may be pending)
        __syncthreads();    // Q visible CTA-wide; score buffer free for reuse

        // ---- hoist Q fragments (2 row-groups x 8 ks) ----
        uint32_t aq[2][8][4];
        #pragma unroll
        for (int rg = 0; rg < 2; ++rg) {
            int arow = rg * 16 + ((lm & 1) << 3) + lr;
            uint32_t arow256 = (uint32_t)arow * 256;
            int ax7 = arow & 7, amc = lm >> 1;
            #pragma unroll
            for (int ks = 0; ks < 8; ++ks) {
                uint32_t ac = (uint32_t)((((2 * ks + amc) ^ ax7) & 15) << 4);
                ldsm4(aq[rg][ks], sb + OFF_Q + arow256 + ac);
            }
        }

        float s[4] = {0.f, 0.f, 0.f, 0.f};

        #pragma unroll
        for (int t = 0; t < NT; ++t) {
            if (t <= 4) cpa_wait<3>();
            else if (t == 5) cpa_wait<2>();
            else if (t == 6) cpa_wait<1>();
            else cpa_wait<0>();

            const uint32_t Kb = myring + (uint32_t)(t & 3) * 2048;
            float acc0[4] = {0.f, 0.f, 0.f, 0.f};
            float acc1[4] = {0.f, 0.f, 0.f, 0.f};

            #pragma unroll
            for (int ks = 0; ks < 8; ks += 2) {
                uint32_t b4[4];   // mats {0,1}: ks lo/hi; {2,3}: ks+1 lo/hi
                uint32_t bc = (uint32_t)((((2 * ks + bsel) ^ brow) & 15) << 4);
                ldsm4(b4, Kb + browoff + bc);
                mma16816(acc0, aq[0][ks],     b4[0], b4[1]);
                mma16816(acc1, aq[1][ks],     b4[0], b4[1]);
                mma16816(acc0, aq[0][ks + 1], b4[2], b4[3]);
                mma16816(acc1, aq[1][ks + 1], b4[2], b4[3]);
            }

            if (t + 4 < NT) pfK(item, t + 4);   // refill slot t&3

            // exp + fp32 sums + fp16 pack + swizzled STS
            uint32_t kb = (uint32_t)t * 256 + kcolbyte;
            float e0, e1;
            e0 = __expf(sc * acc0[0]); e1 = __expf(sc * acc0[1]); s[0] += e0 + e1;
            sts32(scb + (uint32_t)r0 * 2048        + (kb ^ rx), f2h2(e0, e1));
            e0 = __expf(sc * acc0[2]); e1 = __expf(sc * acc0[3]); s[1] += e0 + e1;
            sts32(scb + (uint32_t)(r0 + 8) * 2048  + (kb ^ rx), f2h2(e0, e1));
            e0 = __expf(sc * acc1[0]); e1 = __expf(sc * acc1[1]); s[2] += e0 + e1;
            sts32(scb + (uint32_t)(r0 + 16) * 2048 + (kb ^ rx), f2h2(e0, e1));
            e0 = __expf(sc * acc1[2]); e1 = __expf(sc * acc1[3]); s[3] += e0 + e1;
            sts32(scb + (uint32_t)(r0 + 24) * 2048 + (kb ^ rx), f2h2(e0, e1));
        }

        // ---- prefetch next item's Q + K prologue (overlaps epilogue) ----
        if (next < NITEMS) {
            pfQ(next);
            #pragma unroll
            for (int t = 0; t < 4; ++t) pfK(next, t);
        }

        // ---- row sums: reduce over key-lanes, then over warps ----
        #pragma unroll
        for (int o = 1; o < 4; o <<= 1) {
            s[0] += __shfl_xor_sync(0xFFFFFFFFu, s[0], o);
            s[1] += __shfl_xor_sync(0xFFFFFFFFu, s[1], o);
            s[2] += __shfl_xor_sync(0xFFFFFFFFu, s[2], o);
            s[3] += __shfl_xor_sync(0xFFFFFFFFu, s[3], o);
        }
        if ((lane & 3) == 0) {
            rs[(r0)      * 16 + w] = s[0];
            rs[(r0 + 8)  * 16 + w] = s[1];
            rs[(r0 + 16) * 16 + w] = s[2];
            rs[(r0 + 24) * 16 + w] = s[3];
        }
        __syncthreads();   // publishes all score STS + rs
        // parallel inv: 256 threads, row = tid>>3, each sums 2 partials + shuffle
        if (tid < 256) {
            int row = tid >> 3, pi = tid & 7;
            float2 v = ((const float2*)rs)[row * 8 + pi];
            float tot = v.x + v.y;
            tot += __shfl_xor_sync(0xFFFFFFFFu, tot, 1);
            tot += __shfl_xor_sync(0xFFFFFFFFu, tot, 2);
            tot += __shfl_xor_sync(0xFFFFFFFFu, tot, 4);
            if (pi == 0) inv[row] = 1.0f / tot;
        }
        __syncthreads();

        // ---- coalesced normalize + store ----
        const int row = tid >> 4, cc = tid & 15;
        const float iv = inv[row];
        float* orow = out + ((size_t)bh * Pp + mtile * BM + row) * Pp;
        const uint32_t rbase = scb + (uint32_t)row * 2048;
        const uint32_t rxr = (uint32_t)((row & 7) << 4);
        #pragma unroll
        for (int p = 0; p < 16; ++p) {
            int key = cc * 4 + p * 64;
            uint32_t a, b;
            lds64(a, b, rbase + (((uint32_t)(key * 2)) ^ rxr));
            __half2 ha = *reinterpret_cast<__half2*>(&a);
            __half2 hb = *reinterpret_cast<__half2*>(&b);
            float2 fa = __half22float2(ha);
            float2 fb = __half22float2(hb);
            float4 v = make_float4(fa.x * iv, fa.y * iv, fb.x * iv, fb.y * iv);
            *(float4*)(orow + key) = v;
        }

        item = next;
    }
}

// =================== launch ===================
extern "C" void kernel_launch(void* const* d_in, const int* in_sizes, int n_in,
                              void* d_out, int out_size)
{
    const float* q     = (const float*)d_in[0];
    const float* k     = (const float*)d_in[1];
    const float* scale = (const float*)d_in[2];
    float* out = (float*)d_out;

    silu_split_kernel<<<NELEM / 8 / 256, 256>>>(q, k);

    cudaFuncSetAttribute(attn_mma_kernel,
                         cudaFuncAttributeMaxDynamicSharedMemorySize, SMEM2);
    attn_mma_kernel<<<NCTAS, 512, SMEM2>>>(scale, out);
}